// round 16
// baseline (speedup 1.0000x reference)
#include <cuda_runtime.h>
#include <cstdint>

#define N_NODES  50000
#define E_EDGES  400000
#define G_GRAPHS 64
#define H_DIM    300
#define L_DIM    100
#define TE       64
#define KC       30
#define ATP      68      // transposed activation pitch (floats per k-row)
#define WSLAB    (2 * KC * 16)   // per-warp double-buffered weight slab (floats)
#define NTHREADS 320
#define NWARPS   10
#define PQ_DIM   600     // [P | Q] columns per node

// Scratch
__device__ float g_h1[N_NODES * L_DIM];     // node feats after layer 0
__device__ float g_h2[N_NODES * L_DIM];     // node feats after layer 1
__device__ float g_wc[L_DIM * PQ_DIM];      // [100][600] = [W1a-W1b | W1b]
__device__ float g_pq[N_NODES * PQ_DIM];    // per-node P|Q for layer 1

__global__ void zero_kernel(float* __restrict__ p, int n) {
    int i = blockIdx.x * blockDim.x + threadIdx.x;
    int stride = gridDim.x * blockDim.x;
    for (; i < n; i += stride) p[i] = 0.f;
}

// g_wc[k][c] : c<300 -> W1[k][c] - W1[100+k][c] ; c>=300 -> W1[100+k][c-300]
__global__ void wcomb_kernel(const float* __restrict__ w1, float* __restrict__ wc) {
    int i = blockIdx.x * blockDim.x + threadIdx.x;
    if (i < L_DIM * PQ_DIM) {
        int k = i / PQ_DIM, c = i - k * PQ_DIM;
        wc[i] = (c < H_DIM) ? (w1[k * H_DIM + c] - w1[(L_DIM + k) * H_DIM + c])
                            : w1[(L_DIM + k) * H_DIM + (c - H_DIM)];
    }
}

// ---- packed fp32x2 helpers (Blackwell FFMA2, PTX-only) ----
__device__ __forceinline__ uint64_t f32x2_fma(uint64_t a, uint64_t b, uint64_t c) {
    uint64_t d;
    asm("fma.rn.f32x2 %0, %1, %2, %3;" : "=l"(d) : "l"(a), "l"(b), "l"(c));
    return d;
}
__device__ __forceinline__ void f32x2_unpack(uint64_t v, float& x, float& y) {
    asm("mov.b64 {%0, %1}, %2;" : "=f"(x), "=f"(y) : "l"(v));
}
__device__ __forceinline__ uint64_t f32x2_pack(float x, float y) {
    uint64_t r;
    asm("mov.b64 %0, {%1, %2};" : "=l"(r) : "f"(x), "f"(y));
    return r;
}

// One [64 x NCOLS] GEMM tile on transposed activations:
//   out[c][r] = act( sum_k AsT[k][r] * W[k][c] (+ bias[c]) )
// 320 threads = 10 warps. COLUMN-GROUP SCHEDULE: ceil(NCOLS/16) 16-col groups;
// warp w processes groups w, w+10, ... independently (no block barriers in the
// mainloop; caller syncs around gemm_tile). Within a group, thread (eq, half)
// owns rows 4eq..4eq+3 x cols 8half..8half+7.
// Per k: A = 1x LDS.128 (4 rows, dup'd in regs), B = 2x LDS.128 broadcast,
// 16 FFMA2. Weight K-chunks (length KCL, exact -- no K padding) are
// double-buffered in the warp's private smem slab with register prefetch.
// MODE: 0 = store transposed to DsT[c*ATP+r]
//       1 = clamped atomicMax scatter to OUT[s_dst[r]*NCOLS+c]
//       2 = row store to OUT[(row0+r)*ost+c], guarded by row < N_NODES
template<int KCHUNKS, int KCL, int KTRUE, int NCOLS, int MODE, bool RELU, bool ADD_BIAS>
__device__ __forceinline__ void gemm_tile(
    const float* AsT, const float* __restrict__ W, const float* __restrict__ bias,
    float* DsT, float* s_Bw, const int* s_dst, float* OUT, int row0, int ost)
{
    const int tid  = threadIdx.x;
    const int eq   = tid & 15;    // row quad (rows 4eq..4eq+3)
    const int co   = tid >> 4;
    const int wp   = tid >> 5;    // warp id
    const int lane = tid & 31;
    const int half = co & 1;      // col octet within the 16-col group
    constexpr int NG = (NCOLS + 15) / 16;        // 16-col groups
    constexpr int NPRE = KCL * 16 / 32;          // weight values per lane/chunk
    static_assert((KCL * 16) % 32 == 0, "KCL must be even");

    float* myB = s_Bw + wp * WSLAB;
    const float* Ab = AsT + 4 * eq;

    for (int g = wp; g < NG; g += NWARPS) {
        const int cbase = 16 * g;
        uint64_t acc[4][4];
#pragma unroll
        for (int e = 0; e < 4; e++)
#pragma unroll
            for (int j = 0; j < 4; j++) acc[e][j] = 0ull;

        float pre[NPRE];
        // prefetch chunk 0 (lane covers (kk,c): idx = lane + 32r)
#pragma unroll
        for (int r = 0; r < NPRE; r++) {
            int idx = lane + 32 * r;
            int kk = idx >> 4, c = idx & 15;
            int col = cbase + c;
            pre[r] = (kk < KTRUE && col < NCOLS) ? W[kk * NCOLS + col] : 0.f;
        }
        // store buf0
#pragma unroll
        for (int r = 0; r < NPRE; r++) {
            int idx = lane + 32 * r;
            int kk = idx >> 4, c = idx & 15;
            myB[kk * 16 + c] = pre[r];
        }
        // prefetch chunk 1
        if (KCHUNKS > 1) {
#pragma unroll
            for (int r = 0; r < NPRE; r++) {
                int idx = lane + 32 * r;
                int kk = idx >> 4, c = idx & 15;
                int k = KCL + kk, col = cbase + c;
                pre[r] = (k < KTRUE && col < NCOLS) ? W[k * NCOLS + col] : 0.f;
            }
        }
        __syncwarp();   // buf0 visible warp-wide

        for (int kc = 0; kc < KCHUNKS; kc++) {
            // stage next chunk into the other buffer; prefetch chunk kc+2
            if (kc + 1 < KCHUNKS) {
                float* bnx = myB + ((kc + 1) & 1) * (KCL * 16);
#pragma unroll
                for (int r = 0; r < NPRE; r++) {
                    int idx = lane + 32 * r;
                    int kk = idx >> 4, c = idx & 15;
                    bnx[kk * 16 + c] = pre[r];
                }
                if (kc + 2 < KCHUNKS) {
#pragma unroll
                    for (int r = 0; r < NPRE; r++) {
                        int idx = lane + 32 * r;
                        int kk = idx >> 4, c = idx & 15;
                        int k = (kc + 2) * KCL + kk, col = cbase + c;
                        pre[r] = (k < KTRUE && col < NCOLS) ? W[k * NCOLS + col] : 0.f;
                    }
                }
            }
            const float* Arow = Ab + kc * KCL * ATP;
            const float* Brow = myB + (kc & 1) * (KCL * 16) + 8 * half;
#pragma unroll
            for (int kk = 0; kk < KCL; kk++) {
                // A: one LDS.128 (16B-aligned: ATP*4=272B and 16*eq both /16)
                float4 av = *reinterpret_cast<const float4*>(Arow + kk * ATP);
                uint64_t ap0 = f32x2_pack(av.x, av.x);
                uint64_t ap1 = f32x2_pack(av.y, av.y);
                uint64_t ap2 = f32x2_pack(av.z, av.z);
                uint64_t ap3 = f32x2_pack(av.w, av.w);
                // B: two LDS.128 broadcasts; halves are ready FFMA2 operands
                ulonglong2 b01 = *reinterpret_cast<const ulonglong2*>(Brow + kk * 16);
                ulonglong2 b23 = *reinterpret_cast<const ulonglong2*>(Brow + kk * 16 + 4);
                acc[0][0] = f32x2_fma(ap0, b01.x, acc[0][0]);
                acc[0][1] = f32x2_fma(ap0, b01.y, acc[0][1]);
                acc[0][2] = f32x2_fma(ap0, b23.x, acc[0][2]);
                acc[0][3] = f32x2_fma(ap0, b23.y, acc[0][3]);
                acc[1][0] = f32x2_fma(ap1, b01.x, acc[1][0]);
                acc[1][1] = f32x2_fma(ap1, b01.y, acc[1][1]);
                acc[1][2] = f32x2_fma(ap1, b23.x, acc[1][2]);
                acc[1][3] = f32x2_fma(ap1, b23.y, acc[1][3]);
                acc[2][0] = f32x2_fma(ap2, b01.x, acc[2][0]);
                acc[2][1] = f32x2_fma(ap2, b01.y, acc[2][1]);
                acc[2][2] = f32x2_fma(ap2, b23.x, acc[2][2]);
                acc[2][3] = f32x2_fma(ap2, b23.y, acc[2][3]);
                acc[3][0] = f32x2_fma(ap3, b01.x, acc[3][0]);
                acc[3][1] = f32x2_fma(ap3, b01.y, acc[3][1]);
                acc[3][2] = f32x2_fma(ap3, b23.x, acc[3][2]);
                acc[3][3] = f32x2_fma(ap3, b23.y, acc[3][3]);
            }
            __syncwarp();   // reads of buf kc done; staging may overwrite next iter
        }
        // epilogue: unpack to v[row][col-within-octet]
        float v[4][8];
#pragma unroll
        for (int e = 0; e < 4; e++)
#pragma unroll
            for (int j = 0; j < 4; j++)
                f32x2_unpack(acc[e][j], v[e][2 * j], v[e][2 * j + 1]);
#pragma unroll
        for (int jj = 0; jj < 8; jj++) {
            int c = cbase + 8 * half + jj;
            if (c < NCOLS) {
                float bc = ADD_BIAS ? bias[c] : 0.f;
                float w0 = v[0][jj] + bc, w1 = v[1][jj] + bc;
                float w2 = v[2][jj] + bc, w3 = v[3][jj] + bc;
                if (RELU || MODE == 1) {
                    w0 = fmaxf(w0, 0.f); w1 = fmaxf(w1, 0.f);
                    w2 = fmaxf(w2, 0.f); w3 = fmaxf(w3, 0.f);
                }
                if (MODE == 1) {
                    // relu(segment_max) == atomicMax over clamped msgs into
                    // zero-init buffer; nonneg float order == int order.
                    int* o = reinterpret_cast<int*>(OUT);
                    atomicMax(o + s_dst[4 * eq + 0] * NCOLS + c, __float_as_int(w0));
                    atomicMax(o + s_dst[4 * eq + 1] * NCOLS + c, __float_as_int(w1));
                    atomicMax(o + s_dst[4 * eq + 2] * NCOLS + c, __float_as_int(w2));
                    atomicMax(o + s_dst[4 * eq + 3] * NCOLS + c, __float_as_int(w3));
                } else if (MODE == 2) {
                    int r0 = row0 + 4 * eq;
                    if (r0 + 0 < N_NODES) OUT[(int64_t)(r0 + 0) * ost + c] = w0;
                    if (r0 + 1 < N_NODES) OUT[(int64_t)(r0 + 1) * ost + c] = w1;
                    if (r0 + 2 < N_NODES) OUT[(int64_t)(r0 + 2) * ost + c] = w2;
                    if (r0 + 3 < N_NODES) OUT[(int64_t)(r0 + 3) * ost + c] = w3;
                } else {
                    float* D = DsT + c * ATP + 4 * eq;
                    *reinterpret_cast<uint64_t*>(D)     = f32x2_pack(w0, w1);
                    *reinterpret_cast<uint64_t*>(D + 2) = f32x2_pack(w2, w3);
                }
            }
        }
    }
}

// Layer 0 fused per-edge MLP: gather [x_i, x_j - x_i] (transposed) -> 14 ->
// 300 -> 300 -> 100 -> clamped scatter-max into OUT[dst].
template<int CIN>
__global__ void __launch_bounds__(NTHREADS, 1)
edge_mlp_kernel(const float* __restrict__ X,
                const int* __restrict__ src, const int* __restrict__ dst,
                const float* __restrict__ W1, const float* __restrict__ B1,
                const float* __restrict__ W2, const float* __restrict__ B2,
                const float* __restrict__ W3, const float* __restrict__ B3,
                float* __restrict__ OUT)
{
    constexpr int KIN = 2 * CIN;   // 14, used exactly (KCL = KIN, one chunk)

    extern __shared__ float smem[];
    float* s_uT  = smem;                    // [300][68] transposed act (in / h2)
    float* s_h1T = smem + H_DIM * ATP;      // [300][68] transposed h1
    float* s_Bw  = smem + 2 * H_DIM * ATP;  // NWARPS x [2][KC][16] weight slabs
    int* s_src   = (int*)(s_Bw + NWARPS * WSLAB);
    int* s_dst   = s_src + TE;

    const int tid = threadIdx.x;
    const int e0  = blockIdx.x * TE;        // grid exact: 6250*64 == E_EDGES

    if (tid < TE) {
        s_src[tid] = src[e0 + tid];
        s_dst[tid] = dst[e0 + tid];
    }
    __syncthreads();

    // gather transposed: s_uT[k][e] = x_i[k], s_uT[CIN+k][e] = x_j[k]-x_i[k]
    for (int idx = tid; idx < TE * CIN; idx += NTHREADS) {
        int e = idx & (TE - 1), k = idx >> 6;
        float xi = X[(int64_t)s_dst[e] * CIN + k];
        float xj = X[(int64_t)s_src[e] * CIN + k];
        s_uT[k * ATP + e] = xi;
        s_uT[(CIN + k) * ATP + e] = xj - xi;
    }
    __syncthreads();   // A-tile ready

    gemm_tile<1, KIN, KIN, H_DIM, 0, true, true>(s_uT,  W1, B1, s_h1T, s_Bw, s_dst, nullptr, 0, 0);
    __syncthreads();   // h1 tile ready (and s_uT reads finished)
    gemm_tile<10, KC, H_DIM, H_DIM, 0, true, true>(s_h1T, W2, B2, s_uT, s_Bw, s_dst, nullptr, 0, 0);
    __syncthreads();   // h2 tile ready
    gemm_tile<10, KC, H_DIM, L_DIM, 1, false, true>(s_uT,  W3, B3, nullptr, s_Bw, s_dst, OUT, 0, 0);
}

// Node-side P|Q precompute for layer 1: PQ[n][0:600] = h1[n] @ g_wc.
__global__ void __launch_bounds__(NTHREADS, 1)
node_pq_kernel(const float* __restrict__ H, const float* __restrict__ WC,
               float* __restrict__ PQ)
{
    extern __shared__ float smem[];
    float* s_uT = smem;                       // [100][68] transposed h rows
    float* s_Bw = smem + L_DIM * ATP;         // NWARPS warp slabs

    const int tid = threadIdx.x;
    const int n0  = blockIdx.x * TE;

    // gather: s_uT[k][n] = H[min(n0+n, N-1)][k]  (float4 over k)
    for (int idx = tid; idx < TE * (L_DIM / 4); idx += NTHREADS) {
        int n = idx & (TE - 1), kq = idx >> 6;
        int row = min(n0 + n, N_NODES - 1);
        float4 h = *(const float4*)(H + (int64_t)row * L_DIM + 4 * kq);
        s_uT[(4 * kq + 0) * ATP + n] = h.x;
        s_uT[(4 * kq + 1) * ATP + n] = h.y;
        s_uT[(4 * kq + 2) * ATP + n] = h.z;
        s_uT[(4 * kq + 3) * ATP + n] = h.w;
    }
    __syncthreads();   // A-tile ready

    gemm_tile<5, 20, L_DIM, PQ_DIM, 2, false, false>(
        s_uT, WC, nullptr, nullptr, s_Bw, nullptr, PQ, n0, PQ_DIM);
}

// Layer 1 per-edge MLP with node-decomposed GEMM1:
//   h1 = relu(P[dst] + Q[src] + b1) -> 300 -> 300 -> 100 -> scatter-max.
__global__ void __launch_bounds__(NTHREADS, 1)
edge_mlp2_kernel(const float* __restrict__ PQ,
                 const int* __restrict__ src, const int* __restrict__ dst,
                 const float* __restrict__ B1,
                 const float* __restrict__ W2, const float* __restrict__ B2,
                 const float* __restrict__ W3, const float* __restrict__ B3,
                 float* __restrict__ OUT)
{
    extern __shared__ float smem[];
    float* s_h1T = smem;                    // [300][68] h1
    float* s_uT  = smem + H_DIM * ATP;      // [300][68] h2
    float* s_Bw  = smem + 2 * H_DIM * ATP;  // NWARPS warp slabs
    int* s_src   = (int*)(s_Bw + NWARPS * WSLAB);
    int* s_dst   = s_src + TE;

    const int tid = threadIdx.x;
    const int e0  = blockIdx.x * TE;

    if (tid < TE) {
        s_src[tid] = src[e0 + tid];
        s_dst[tid] = dst[e0 + tid];
    }
    __syncthreads();

    // gather-add: s_h1T[k][e] = relu(P[dst][k] + Q[src][k] + b1[k])
    for (int idx = tid; idx < TE * (H_DIM / 4); idx += NTHREADS) {
        int e = idx & (TE - 1), kq = idx >> 6;
        const float4 pd = *(const float4*)(PQ + (int64_t)s_dst[e] * PQ_DIM + 4 * kq);
        const float4 qs = *(const float4*)(PQ + (int64_t)s_src[e] * PQ_DIM + H_DIM + 4 * kq);
        const float4 bb = *(const float4*)(B1 + 4 * kq);
        s_h1T[(4 * kq + 0) * ATP + e] = fmaxf(pd.x + qs.x + bb.x, 0.f);
        s_h1T[(4 * kq + 1) * ATP + e] = fmaxf(pd.y + qs.y + bb.y, 0.f);
        s_h1T[(4 * kq + 2) * ATP + e] = fmaxf(pd.z + qs.z + bb.z, 0.f);
        s_h1T[(4 * kq + 3) * ATP + e] = fmaxf(pd.w + qs.w + bb.w, 0.f);
    }
    __syncthreads();   // A-tile ready

    gemm_tile<10, KC, H_DIM, H_DIM, 0, true, true>(s_h1T, W2, B2, s_uT, s_Bw, s_dst, nullptr, 0, 0);
    __syncthreads();   // h2 tile ready
    gemm_tile<10, KC, H_DIM, L_DIM, 1, false, true>(s_uT,  W3, B3, nullptr, s_Bw, s_dst, OUT, 0, 0);
}

// One block per graph: contiguous segment (batch sorted) -> add/mean/max
// pooling -> 302 -> 100 -> 100 -> 2 MLP.
__global__ void pool_mlp_kernel(const float* __restrict__ H2,
                                const int* __restrict__ batch,
                                const float* __restrict__ u,
                                const float* __restrict__ w1, const float* __restrict__ b1,
                                const float* __restrict__ w2, const float* __restrict__ b2,
                                const float* __restrict__ w3, const float* __restrict__ b3,
                                float* __restrict__ out)
{
    const int g = blockIdx.x;
    const int t = threadIdx.x;
    __shared__ float p[304];
    __shared__ float q1[100];
    __shared__ float q2[100];

    int s, e2;
    { int a = 0, b = N_NODES; while (a < b) { int m = (a + b) >> 1; if (batch[m] < g) a = m + 1; else b = m; } s = a; }
    { int a = 0, b = N_NODES; while (a < b) { int m = (a + b) >> 1; if (batch[m] < g + 1) a = m + 1; else b = m; } e2 = a; }
    int cnt = e2 - s;

    if (t < L_DIM) {
        float sm = 0.f, mx = 0.f;
        for (int i = s; i < e2; i++) {
            float v = H2[i * L_DIM + t];
            sm += v;
            mx = fmaxf(mx, v);
        }
        p[t] = sm;
        p[L_DIM + t] = sm / fmaxf((float)cnt, 1.0f);
        p[2 * L_DIM + t] = (cnt > 0) ? mx : 0.f;
    }
    if (t < 2) p[3 * L_DIM + t] = u[g * 2 + t];
    __syncthreads();

    if (t < L_DIM) {
        float acc = b1[t];
        for (int k = 0; k < 3 * L_DIM + 2; k++) acc = fmaf(p[k], w1[k * L_DIM + t], acc);
        q1[t] = fmaxf(acc, 0.f);
    }
    __syncthreads();
    if (t < L_DIM) {
        float acc = b2[t];
        for (int k = 0; k < L_DIM; k++) acc = fmaf(q1[k], w2[k * L_DIM + t], acc);
        q2[t] = fmaxf(acc, 0.f);
    }
    __syncthreads();
    if (t < 2) {
        float acc = b3[t];
        for (int k = 0; k < L_DIM; k++) acc = fmaf(q2[k], w3[k * 2 + t], acc);
        out[g * 2 + t] = acc;
    }
}

extern "C" void kernel_launch(void* const* d_in, const int* in_sizes, int n_in,
                              void* d_out, int out_size)
{
    const float* x     = (const float*)d_in[0];
    const int*   ei    = (const int*)d_in[1];
    const int*   batch = (const int*)d_in[2];
    const float* u     = (const float*)d_in[3];
    const float* l0w1  = (const float*)d_in[4];
    const float* l0b1  = (const float*)d_in[5];
    const float* l0w2  = (const float*)d_in[6];
    const float* l0b2  = (const float*)d_in[7];
    const float* l0w3  = (const float*)d_in[8];
    const float* l0b3  = (const float*)d_in[9];
    const float* l1w1  = (const float*)d_in[10];
    const float* l1b1  = (const float*)d_in[11];
    const float* l1w2  = (const float*)d_in[12];
    const float* l1b2  = (const float*)d_in[13];
    const float* l1w3  = (const float*)d_in[14];
    const float* l1b3  = (const float*)d_in[15];
    const float* lw1   = (const float*)d_in[16];
    const float* lb1   = (const float*)d_in[17];
    const float* lw2   = (const float*)d_in[18];
    const float* lb2   = (const float*)d_in[19];
    const float* lw3   = (const float*)d_in[20];
    const float* lb3   = (const float*)d_in[21];
    float* out = (float*)d_out;

    const int* src = ei;
    const int* dst = ei + E_EDGES;

    float *h1p, *h2p, *wcp, *pqp;
    cudaGetSymbolAddress((void**)&h1p, g_h1);
    cudaGetSymbolAddress((void**)&h2p, g_h2);
    cudaGetSymbolAddress((void**)&wcp, g_wc);
    cudaGetSymbolAddress((void**)&pqp, g_pq);

    const int smem_edge = (2 * H_DIM * ATP + NWARPS * WSLAB) * (int)sizeof(float)
                        + 2 * TE * (int)sizeof(int);
    const int smem_node = (L_DIM * ATP + NWARPS * WSLAB) * (int)sizeof(float);

    cudaFuncSetAttribute(edge_mlp_kernel<7>, cudaFuncAttributeMaxDynamicSharedMemorySize, smem_edge);
    cudaFuncSetAttribute(edge_mlp2_kernel,   cudaFuncAttributeMaxDynamicSharedMemorySize, smem_edge);
    cudaFuncSetAttribute(node_pq_kernel,     cudaFuncAttributeMaxDynamicSharedMemorySize, smem_node);

    zero_kernel<<<304, 256>>>(h1p, N_NODES * L_DIM);
    zero_kernel<<<304, 256>>>(h2p, N_NODES * L_DIM);
    wcomb_kernel<<<(L_DIM * PQ_DIM + 255) / 256, 256>>>(l1w1, wcp);

    const int nblk = E_EDGES / TE;   // exact
    edge_mlp_kernel<7><<<nblk, NTHREADS, smem_edge>>>(
        x, src, dst, l0w1, l0b1, l0w2, l0b2, l0w3, l0b3, h1p);

    node_pq_kernel<<<(N_NODES + TE - 1) / TE, NTHREADS, smem_node>>>(h1p, wcp, pqp);

    edge_mlp2_kernel<<<nblk, NTHREADS, smem_edge>>>(
        pqp, src, dst, l1b1, l1w2, l1b2, l1w3, l1b3, h2p);

    pool_mlp_kernel<<<G_GRAPHS, 128>>>(
        h2p, batch, u, lw1, lb1, lw2, lb2, lw3, lb3, out);
}

// round 17
// speedup vs baseline: 1.1027x; 1.1027x over previous
#include <cuda_runtime.h>
#include <cstdint>

#define N_NODES  50000
#define E_EDGES  400000
#define G_GRAPHS 64
#define H_DIM    300
#define L_DIM    100
#define TE       64
#define KC       30
#define ATP      68      // transposed activation pitch (floats per k-row)
#define WSLAB    (2 * KC * 16)   // per-warp double-buffered weight slab (floats)
#define NTHREADS 384
#define NWARPS   12
#define PQ_DIM   600     // [P | Q] columns per node

// Scratch
__device__ float g_h1[N_NODES * L_DIM];     // node feats after layer 0
__device__ float g_h2[N_NODES * L_DIM];     // node feats after layer 1
__device__ float g_wc[L_DIM * PQ_DIM];      // [100][600] = [W1a-W1b | W1b]
__device__ float g_pq[N_NODES * PQ_DIM];    // per-node P|Q for layer 1

__global__ void zero_kernel(float* __restrict__ p, int n) {
    int i = blockIdx.x * blockDim.x + threadIdx.x;
    int stride = gridDim.x * blockDim.x;
    for (; i < n; i += stride) p[i] = 0.f;
}

// g_wc[k][c] : c<300 -> W1[k][c] - W1[100+k][c] ; c>=300 -> W1[100+k][c-300]
__global__ void wcomb_kernel(const float* __restrict__ w1, float* __restrict__ wc) {
    int i = blockIdx.x * blockDim.x + threadIdx.x;
    if (i < L_DIM * PQ_DIM) {
        int k = i / PQ_DIM, c = i - k * PQ_DIM;
        wc[i] = (c < H_DIM) ? (w1[k * H_DIM + c] - w1[(L_DIM + k) * H_DIM + c])
                            : w1[(L_DIM + k) * H_DIM + (c - H_DIM)];
    }
}

// ---- packed fp32x2 helpers (Blackwell FFMA2, PTX-only) ----
__device__ __forceinline__ uint64_t f32x2_fma(uint64_t a, uint64_t b, uint64_t c) {
    uint64_t d;
    asm("fma.rn.f32x2 %0, %1, %2, %3;" : "=l"(d) : "l"(a), "l"(b), "l"(c));
    return d;
}
__device__ __forceinline__ void f32x2_unpack(uint64_t v, float& x, float& y) {
    asm("mov.b64 {%0, %1}, %2;" : "=f"(x), "=f"(y) : "l"(v));
}
__device__ __forceinline__ uint64_t f32x2_pack(float x, float y) {
    uint64_t r;
    asm("mov.b64 %0, {%1, %2};" : "=l"(r) : "f"(x), "f"(y));
    return r;
}

// One [64 x NCOLS] GEMM tile on transposed activations:
//   out[c][r] = act( sum_k AsT[k][r] * W[k][c] (+ bias[c]) )
// 384 threads = 12 warps (3 per SMSP -- keeps SMSPs balanced). COLUMN-GROUP
// SCHEDULE: ceil(NCOLS/16) 16-col groups; warp w processes groups w, w+12, ...
// independently (no block barriers in the mainloop; caller syncs around
// gemm_tile). Within a group, thread (eq, half) owns rows 4eq..4eq+3 x cols
// 8half..8half+7.
// Per k: A = 1x LDS.128 (4 rows, dup'd in regs), B = 2x LDS.128 broadcast,
// 16 FFMA2. Weight K-chunks (length KCL, exact -- no K padding) are
// double-buffered in the warp's private smem slab with register prefetch.
// MODE: 0 = store transposed to DsT[c*ATP+r]
//       1 = clamped atomicMax scatter to OUT[s_dst[r]*NCOLS+c]
//       2 = row store to OUT[(row0+r)*ost+c], guarded by row < N_NODES
template<int KCHUNKS, int KCL, int KTRUE, int NCOLS, int MODE, bool RELU, bool ADD_BIAS>
__device__ __forceinline__ void gemm_tile(
    const float* AsT, const float* __restrict__ W, const float* __restrict__ bias,
    float* DsT, float* s_Bw, const int* s_dst, float* OUT, int row0, int ost)
{
    const int tid  = threadIdx.x;
    const int eq   = tid & 15;    // row quad (rows 4eq..4eq+3)
    const int co   = tid >> 4;
    const int wp   = tid >> 5;    // warp id
    const int lane = tid & 31;
    const int half = co & 1;      // col octet within the 16-col group
    constexpr int NG = (NCOLS + 15) / 16;        // 16-col groups
    constexpr int NPRE = KCL * 16 / 32;          // weight values per lane/chunk
    static_assert((KCL * 16) % 32 == 0, "KCL must be even");

    float* myB = s_Bw + wp * WSLAB;
    const float* Ab = AsT + 4 * eq;

    for (int g = wp; g < NG; g += NWARPS) {
        const int cbase = 16 * g;
        uint64_t acc[4][4];
#pragma unroll
        for (int e = 0; e < 4; e++)
#pragma unroll
            for (int j = 0; j < 4; j++) acc[e][j] = 0ull;

        float pre[NPRE];
        // prefetch chunk 0 (lane covers (kk,c): idx = lane + 32r)
#pragma unroll
        for (int r = 0; r < NPRE; r++) {
            int idx = lane + 32 * r;
            int kk = idx >> 4, c = idx & 15;
            int col = cbase + c;
            pre[r] = (kk < KTRUE && col < NCOLS) ? W[kk * NCOLS + col] : 0.f;
        }
        // store buf0
#pragma unroll
        for (int r = 0; r < NPRE; r++) {
            int idx = lane + 32 * r;
            int kk = idx >> 4, c = idx & 15;
            myB[kk * 16 + c] = pre[r];
        }
        // prefetch chunk 1
        if (KCHUNKS > 1) {
#pragma unroll
            for (int r = 0; r < NPRE; r++) {
                int idx = lane + 32 * r;
                int kk = idx >> 4, c = idx & 15;
                int k = KCL + kk, col = cbase + c;
                pre[r] = (k < KTRUE && col < NCOLS) ? W[k * NCOLS + col] : 0.f;
            }
        }
        __syncwarp();   // buf0 visible warp-wide

        for (int kc = 0; kc < KCHUNKS; kc++) {
            // stage next chunk into the other buffer; prefetch chunk kc+2
            if (kc + 1 < KCHUNKS) {
                float* bnx = myB + ((kc + 1) & 1) * (KCL * 16);
#pragma unroll
                for (int r = 0; r < NPRE; r++) {
                    int idx = lane + 32 * r;
                    int kk = idx >> 4, c = idx & 15;
                    bnx[kk * 16 + c] = pre[r];
                }
                if (kc + 2 < KCHUNKS) {
#pragma unroll
                    for (int r = 0; r < NPRE; r++) {
                        int idx = lane + 32 * r;
                        int kk = idx >> 4, c = idx & 15;
                        int k = (kc + 2) * KCL + kk, col = cbase + c;
                        pre[r] = (k < KTRUE && col < NCOLS) ? W[k * NCOLS + col] : 0.f;
                    }
                }
            }
            const float* Arow = Ab + kc * KCL * ATP;
            const float* Brow = myB + (kc & 1) * (KCL * 16) + 8 * half;
#pragma unroll
            for (int kk = 0; kk < KCL; kk++) {
                // A: one LDS.128 (16B-aligned: ATP*4=272B and 16*eq both /16)
                float4 av = *reinterpret_cast<const float4*>(Arow + kk * ATP);
                uint64_t ap0 = f32x2_pack(av.x, av.x);
                uint64_t ap1 = f32x2_pack(av.y, av.y);
                uint64_t ap2 = f32x2_pack(av.z, av.z);
                uint64_t ap3 = f32x2_pack(av.w, av.w);
                // B: two LDS.128 broadcasts; halves are ready FFMA2 operands
                ulonglong2 b01 = *reinterpret_cast<const ulonglong2*>(Brow + kk * 16);
                ulonglong2 b23 = *reinterpret_cast<const ulonglong2*>(Brow + kk * 16 + 4);
                acc[0][0] = f32x2_fma(ap0, b01.x, acc[0][0]);
                acc[0][1] = f32x2_fma(ap0, b01.y, acc[0][1]);
                acc[0][2] = f32x2_fma(ap0, b23.x, acc[0][2]);
                acc[0][3] = f32x2_fma(ap0, b23.y, acc[0][3]);
                acc[1][0] = f32x2_fma(ap1, b01.x, acc[1][0]);
                acc[1][1] = f32x2_fma(ap1, b01.y, acc[1][1]);
                acc[1][2] = f32x2_fma(ap1, b23.x, acc[1][2]);
                acc[1][3] = f32x2_fma(ap1, b23.y, acc[1][3]);
                acc[2][0] = f32x2_fma(ap2, b01.x, acc[2][0]);
                acc[2][1] = f32x2_fma(ap2, b01.y, acc[2][1]);
                acc[2][2] = f32x2_fma(ap2, b23.x, acc[2][2]);
                acc[2][3] = f32x2_fma(ap2, b23.y, acc[2][3]);
                acc[3][0] = f32x2_fma(ap3, b01.x, acc[3][0]);
                acc[3][1] = f32x2_fma(ap3, b01.y, acc[3][1]);
                acc[3][2] = f32x2_fma(ap3, b23.x, acc[3][2]);
                acc[3][3] = f32x2_fma(ap3, b23.y, acc[3][3]);
            }
            __syncwarp();   // reads of buf kc done; staging may overwrite next iter
        }
        // epilogue: unpack to v[row][col-within-octet]
        float v[4][8];
#pragma unroll
        for (int e = 0; e < 4; e++)
#pragma unroll
            for (int j = 0; j < 4; j++)
                f32x2_unpack(acc[e][j], v[e][2 * j], v[e][2 * j + 1]);
#pragma unroll
        for (int jj = 0; jj < 8; jj++) {
            int c = cbase + 8 * half + jj;
            if (c < NCOLS) {
                float bc = ADD_BIAS ? bias[c] : 0.f;
                float w0 = v[0][jj] + bc, w1 = v[1][jj] + bc;
                float w2 = v[2][jj] + bc, w3 = v[3][jj] + bc;
                if (RELU || MODE == 1) {
                    w0 = fmaxf(w0, 0.f); w1 = fmaxf(w1, 0.f);
                    w2 = fmaxf(w2, 0.f); w3 = fmaxf(w3, 0.f);
                }
                if (MODE == 1) {
                    // relu(segment_max) == atomicMax over clamped msgs into
                    // zero-init buffer; nonneg float order == int order.
                    int* o = reinterpret_cast<int*>(OUT);
                    atomicMax(o + s_dst[4 * eq + 0] * NCOLS + c, __float_as_int(w0));
                    atomicMax(o + s_dst[4 * eq + 1] * NCOLS + c, __float_as_int(w1));
                    atomicMax(o + s_dst[4 * eq + 2] * NCOLS + c, __float_as_int(w2));
                    atomicMax(o + s_dst[4 * eq + 3] * NCOLS + c, __float_as_int(w3));
                } else if (MODE == 2) {
                    int r0 = row0 + 4 * eq;
                    if (r0 + 0 < N_NODES) OUT[(int64_t)(r0 + 0) * ost + c] = w0;
                    if (r0 + 1 < N_NODES) OUT[(int64_t)(r0 + 1) * ost + c] = w1;
                    if (r0 + 2 < N_NODES) OUT[(int64_t)(r0 + 2) * ost + c] = w2;
                    if (r0 + 3 < N_NODES) OUT[(int64_t)(r0 + 3) * ost + c] = w3;
                } else {
                    float* D = DsT + c * ATP + 4 * eq;
                    *reinterpret_cast<uint64_t*>(D)     = f32x2_pack(w0, w1);
                    *reinterpret_cast<uint64_t*>(D + 2) = f32x2_pack(w2, w3);
                }
            }
        }
    }
}

// Layer 0 fused per-edge MLP: gather [x_i, x_j - x_i] (transposed) -> 14 ->
// 300 -> 300 -> 100 -> clamped scatter-max into OUT[dst].
template<int CIN>
__global__ void __launch_bounds__(NTHREADS, 1)
edge_mlp_kernel(const float* __restrict__ X,
                const int* __restrict__ src, const int* __restrict__ dst,
                const float* __restrict__ W1, const float* __restrict__ B1,
                const float* __restrict__ W2, const float* __restrict__ B2,
                const float* __restrict__ W3, const float* __restrict__ B3,
                float* __restrict__ OUT)
{
    constexpr int KIN = 2 * CIN;   // 14, used exactly (KCL = KIN, one chunk)

    extern __shared__ float smem[];
    float* s_uT  = smem;                    // [300][68] transposed act (in / h2)
    float* s_h1T = smem + H_DIM * ATP;      // [300][68] transposed h1
    float* s_Bw  = smem + 2 * H_DIM * ATP;  // NWARPS x [2][KC][16] weight slabs
    int* s_src   = (int*)(s_Bw + NWARPS * WSLAB);
    int* s_dst   = s_src + TE;

    const int tid = threadIdx.x;
    const int e0  = blockIdx.x * TE;        // grid exact: 6250*64 == E_EDGES

    if (tid < TE) {
        s_src[tid] = src[e0 + tid];
        s_dst[tid] = dst[e0 + tid];
    }
    __syncthreads();

    // gather transposed: s_uT[k][e] = x_i[k], s_uT[CIN+k][e] = x_j[k]-x_i[k]
    for (int idx = tid; idx < TE * CIN; idx += NTHREADS) {
        int e = idx & (TE - 1), k = idx >> 6;
        float xi = X[(int64_t)s_dst[e] * CIN + k];
        float xj = X[(int64_t)s_src[e] * CIN + k];
        s_uT[k * ATP + e] = xi;
        s_uT[(CIN + k) * ATP + e] = xj - xi;
    }
    __syncthreads();   // A-tile ready

    gemm_tile<1, KIN, KIN, H_DIM, 0, true, true>(s_uT,  W1, B1, s_h1T, s_Bw, s_dst, nullptr, 0, 0);
    __syncthreads();   // h1 tile ready (and s_uT reads finished)
    gemm_tile<10, KC, H_DIM, H_DIM, 0, true, true>(s_h1T, W2, B2, s_uT, s_Bw, s_dst, nullptr, 0, 0);
    __syncthreads();   // h2 tile ready
    gemm_tile<10, KC, H_DIM, L_DIM, 1, false, true>(s_uT,  W3, B3, nullptr, s_Bw, s_dst, OUT, 0, 0);
}

// Node-side P|Q precompute for layer 1: PQ[n][0:600] = h1[n] @ g_wc.
__global__ void __launch_bounds__(NTHREADS, 1)
node_pq_kernel(const float* __restrict__ H, const float* __restrict__ WC,
               float* __restrict__ PQ)
{
    extern __shared__ float smem[];
    float* s_uT = smem;                       // [100][68] transposed h rows
    float* s_Bw = smem + L_DIM * ATP;         // NWARPS warp slabs

    const int tid = threadIdx.x;
    const int n0  = blockIdx.x * TE;

    // gather: s_uT[k][n] = H[min(n0+n, N-1)][k]  (float4 over k)
    for (int idx = tid; idx < TE * (L_DIM / 4); idx += NTHREADS) {
        int n = idx & (TE - 1), kq = idx >> 6;
        int row = min(n0 + n, N_NODES - 1);
        float4 h = *(const float4*)(H + (int64_t)row * L_DIM + 4 * kq);
        s_uT[(4 * kq + 0) * ATP + n] = h.x;
        s_uT[(4 * kq + 1) * ATP + n] = h.y;
        s_uT[(4 * kq + 2) * ATP + n] = h.z;
        s_uT[(4 * kq + 3) * ATP + n] = h.w;
    }
    __syncthreads();   // A-tile ready

    gemm_tile<5, 20, L_DIM, PQ_DIM, 2, false, false>(
        s_uT, WC, nullptr, nullptr, s_Bw, nullptr, PQ, n0, PQ_DIM);
}

// Layer 1 per-edge MLP with node-decomposed GEMM1:
//   h1 = relu(P[dst] + Q[src] + b1) -> 300 -> 300 -> 100 -> scatter-max.
__global__ void __launch_bounds__(NTHREADS, 1)
edge_mlp2_kernel(const float* __restrict__ PQ,
                 const int* __restrict__ src, const int* __restrict__ dst,
                 const float* __restrict__ B1,
                 const float* __restrict__ W2, const float* __restrict__ B2,
                 const float* __restrict__ W3, const float* __restrict__ B3,
                 float* __restrict__ OUT)
{
    extern __shared__ float smem[];
    float* s_h1T = smem;                    // [300][68] h1
    float* s_uT  = smem + H_DIM * ATP;      // [300][68] h2
    float* s_Bw  = smem + 2 * H_DIM * ATP;  // NWARPS warp slabs
    int* s_src   = (int*)(s_Bw + NWARPS * WSLAB);
    int* s_dst   = s_src + TE;

    const int tid = threadIdx.x;
    const int e0  = blockIdx.x * TE;

    if (tid < TE) {
        s_src[tid] = src[e0 + tid];
        s_dst[tid] = dst[e0 + tid];
    }
    __syncthreads();

    // gather-add: s_h1T[k][e] = relu(P[dst][k] + Q[src][k] + b1[k])
    for (int idx = tid; idx < TE * (H_DIM / 4); idx += NTHREADS) {
        int e = idx & (TE - 1), kq = idx >> 6;
        const float4 pd = *(const float4*)(PQ + (int64_t)s_dst[e] * PQ_DIM + 4 * kq);
        const float4 qs = *(const float4*)(PQ + (int64_t)s_src[e] * PQ_DIM + H_DIM + 4 * kq);
        const float4 bb = *(const float4*)(B1 + 4 * kq);
        s_h1T[(4 * kq + 0) * ATP + e] = fmaxf(pd.x + qs.x + bb.x, 0.f);
        s_h1T[(4 * kq + 1) * ATP + e] = fmaxf(pd.y + qs.y + bb.y, 0.f);
        s_h1T[(4 * kq + 2) * ATP + e] = fmaxf(pd.z + qs.z + bb.z, 0.f);
        s_h1T[(4 * kq + 3) * ATP + e] = fmaxf(pd.w + qs.w + bb.w, 0.f);
    }
    __syncthreads();   // A-tile ready

    gemm_tile<10, KC, H_DIM, H_DIM, 0, true, true>(s_h1T, W2, B2, s_uT, s_Bw, s_dst, nullptr, 0, 0);
    __syncthreads();   // h2 tile ready
    gemm_tile<10, KC, H_DIM, L_DIM, 1, false, true>(s_uT,  W3, B3, nullptr, s_Bw, s_dst, OUT, 0, 0);
}

// One block per graph: contiguous segment (batch sorted) -> add/mean/max
// pooling -> 302 -> 100 -> 100 -> 2 MLP.
__global__ void pool_mlp_kernel(const float* __restrict__ H2,
                                const int* __restrict__ batch,
                                const float* __restrict__ u,
                                const float* __restrict__ w1, const float* __restrict__ b1,
                                const float* __restrict__ w2, const float* __restrict__ b2,
                                const float* __restrict__ w3, const float* __restrict__ b3,
                                float* __restrict__ out)
{
    const int g = blockIdx.x;
    const int t = threadIdx.x;
    __shared__ float p[304];
    __shared__ float q1[100];
    __shared__ float q2[100];

    int s, e2;
    { int a = 0, b = N_NODES; while (a < b) { int m = (a + b) >> 1; if (batch[m] < g) a = m + 1; else b = m; } s = a; }
    { int a = 0, b = N_NODES; while (a < b) { int m = (a + b) >> 1; if (batch[m] < g + 1) a = m + 1; else b = m; } e2 = a; }
    int cnt = e2 - s;

    if (t < L_DIM) {
        float sm = 0.f, mx = 0.f;
        for (int i = s; i < e2; i++) {
            float v = H2[i * L_DIM + t];
            sm += v;
            mx = fmaxf(mx, v);
        }
        p[t] = sm;
        p[L_DIM + t] = sm / fmaxf((float)cnt, 1.0f);
        p[2 * L_DIM + t] = (cnt > 0) ? mx : 0.f;
    }
    if (t < 2) p[3 * L_DIM + t] = u[g * 2 + t];
    __syncthreads();

    if (t < L_DIM) {
        float acc = b1[t];
        for (int k = 0; k < 3 * L_DIM + 2; k++) acc = fmaf(p[k], w1[k * L_DIM + t], acc);
        q1[t] = fmaxf(acc, 0.f);
    }
    __syncthreads();
    if (t < L_DIM) {
        float acc = b2[t];
        for (int k = 0; k < L_DIM; k++) acc = fmaf(q1[k], w2[k * L_DIM + t], acc);
        q2[t] = fmaxf(acc, 0.f);
    }
    __syncthreads();
    if (t < 2) {
        float acc = b3[t];
        for (int k = 0; k < L_DIM; k++) acc = fmaf(q2[k], w3[k * 2 + t], acc);
        out[g * 2 + t] = acc;
    }
}

extern "C" void kernel_launch(void* const* d_in, const int* in_sizes, int n_in,
                              void* d_out, int out_size)
{
    const float* x     = (const float*)d_in[0];
    const int*   ei    = (const int*)d_in[1];
    const int*   batch = (const int*)d_in[2];
    const float* u     = (const float*)d_in[3];
    const float* l0w1  = (const float*)d_in[4];
    const float* l0b1  = (const float*)d_in[5];
    const float* l0w2  = (const float*)d_in[6];
    const float* l0b2  = (const float*)d_in[7];
    const float* l0w3  = (const float*)d_in[8];
    const float* l0b3  = (const float*)d_in[9];
    const float* l1w1  = (const float*)d_in[10];
    const float* l1b1  = (const float*)d_in[11];
    const float* l1w2  = (const float*)d_in[12];
    const float* l1b2  = (const float*)d_in[13];
    const float* l1w3  = (const float*)d_in[14];
    const float* l1b3  = (const float*)d_in[15];
    const float* lw1   = (const float*)d_in[16];
    const float* lb1   = (const float*)d_in[17];
    const float* lw2   = (const float*)d_in[18];
    const float* lb2   = (const float*)d_in[19];
    const float* lw3   = (const float*)d_in[20];
    const float* lb3   = (const float*)d_in[21];
    float* out = (float*)d_out;

    const int* src = ei;
    const int* dst = ei + E_EDGES;

    float *h1p, *h2p, *wcp, *pqp;
    cudaGetSymbolAddress((void**)&h1p, g_h1);
    cudaGetSymbolAddress((void**)&h2p, g_h2);
    cudaGetSymbolAddress((void**)&wcp, g_wc);
    cudaGetSymbolAddress((void**)&pqp, g_pq);

    const int smem_edge = (2 * H_DIM * ATP + NWARPS * WSLAB) * (int)sizeof(float)
                        + 2 * TE * (int)sizeof(int);
    const int smem_node = (L_DIM * ATP + NWARPS * WSLAB) * (int)sizeof(float);

    cudaFuncSetAttribute(edge_mlp_kernel<7>, cudaFuncAttributeMaxDynamicSharedMemorySize, smem_edge);
    cudaFuncSetAttribute(edge_mlp2_kernel,   cudaFuncAttributeMaxDynamicSharedMemorySize, smem_edge);
    cudaFuncSetAttribute(node_pq_kernel,     cudaFuncAttributeMaxDynamicSharedMemorySize, smem_node);

    zero_kernel<<<304, 256>>>(h1p, N_NODES * L_DIM);
    zero_kernel<<<304, 256>>>(h2p, N_NODES * L_DIM);
    wcomb_kernel<<<(L_DIM * PQ_DIM + 255) / 256, 256>>>(l1w1, wcp);

    const int nblk = E_EDGES / TE;   // exact
    edge_mlp_kernel<7><<<nblk, NTHREADS, smem_edge>>>(
        x, src, dst, l0w1, l0b1, l0w2, l0b2, l0w3, l0b3, h1p);

    node_pq_kernel<<<(N_NODES + TE - 1) / TE, NTHREADS, smem_node>>>(h1p, wcp, pqp);

    edge_mlp2_kernel<<<nblk, NTHREADS, smem_edge>>>(
        pqp, src, dst, l1b1, l1w2, l1b2, l1w3, l1b3, h2p);

    pool_mlp_kernel<<<G_GRAPHS, 128>>>(
        h2p, batch, u, lw1, lb1, lw2, lb2, lw3, lb3, out);
}